// round 7
// baseline (speedup 1.0000x reference)
#include <cuda_runtime.h>
#include <cuda_bf16.h>
#include <cstdint>
#include <math.h>

// Problem dims
#define BB 64
#define TT 512
#define DD 512
#define HH 512
#define NG 2048          // 4*H gate columns

// Recurrent kernel partitioning
#define GCTA 128
#define JW   4
#define GC   16
#define HP   520         // padded bf16 row stride for ldmatrix tiles

// ---------------------------------------------------------------------------
// Device scratch (allocation-free per harness rules)
// ---------------------------------------------------------------------------
__device__ float g_xw[(size_t)TT * BB * NG];          // [m=t*64+r][2048] fp32 (bias incl.)
__device__ unsigned long long g_bar;                  // grid barrier counter
__device__ __nv_bfloat16 g_xhi[(size_t)TT * BB * DD]; // X split hi [32768,512]
__device__ __nv_bfloat16 g_xlo[(size_t)TT * BB * DD]; // X split lo
__device__ __nv_bfloat16 g_wthi[(size_t)NG * DD];     // Wx^T hi [2048,512]
__device__ __nv_bfloat16 g_wtlo[(size_t)NG * DD];     // Wx^T lo
__device__ __nv_bfloat16 g_hbf_hi[2][BB * HH];        // h split hi, [r][k], dbl-buf
__device__ __nv_bfloat16 g_hbf_lo[2][BB * HH];        // h split lo

__device__ __forceinline__ float sigf(float x) {
    return 1.0f / (1.0f + __expf(-x));
}

__device__ __forceinline__ uint32_t smem_u32(const void* p) {
    uint32_t a;
    asm("{ .reg .u64 t; cvta.to.shared.u64 t, %1; cvt.u32.u64 %0, t; }"
        : "=r"(a) : "l"(p));
    return a;
}

// ---------------------------------------------------------------------------
// mma.sync / ldmatrix / cp.async helpers (baseline PTX, plain sm_103 target)
// ---------------------------------------------------------------------------
__device__ __forceinline__ void ldsm_x4(uint32_t& r0, uint32_t& r1,
                                        uint32_t& r2, uint32_t& r3,
                                        uint32_t addr) {
    asm volatile("ldmatrix.sync.aligned.m8n8.x4.shared.b16 {%0,%1,%2,%3}, [%4];"
                 : "=r"(r0), "=r"(r1), "=r"(r2), "=r"(r3) : "r"(addr));
}
__device__ __forceinline__ void ldsm_x2(uint32_t& r0, uint32_t& r1,
                                        uint32_t addr) {
    asm volatile("ldmatrix.sync.aligned.m8n8.x2.shared.b16 {%0,%1}, [%2];"
                 : "=r"(r0), "=r"(r1) : "r"(addr));
}
__device__ __forceinline__ void mma16816(float* c, const uint32_t* a,
                                         const uint32_t* b) {
    asm volatile(
        "mma.sync.aligned.m16n8k16.row.col.f32.bf16.bf16.f32 "
        "{%0,%1,%2,%3}, {%4,%5,%6,%7}, {%8,%9}, {%0,%1,%2,%3};"
        : "+f"(c[0]), "+f"(c[1]), "+f"(c[2]), "+f"(c[3])
        : "r"(a[0]), "r"(a[1]), "r"(a[2]), "r"(a[3]), "r"(b[0]), "r"(b[1]));
}
#define CP_ASYNC16(dst_u32, src_ptr) \
    asm volatile("cp.async.cg.shared.global [%0], [%1], 16;" \
                 :: "r"(dst_u32), "l"(src_ptr))
#define CP_COMMIT() asm volatile("cp.async.commit_group;" ::: "memory")
#define CP_WAIT(N)  asm volatile("cp.async.wait_group %0;" :: "n"(N) : "memory")

// ---------------------------------------------------------------------------
// Kernel 0a: bf16 hi/lo split conversion of X and Wx^T.
// ---------------------------------------------------------------------------
__global__ void __launch_bounds__(256) conv_kernel(const float* __restrict__ x,
                                                   const float* __restrict__ W) {
    const size_t stride = (size_t)gridDim.x * blockDim.x;
    const size_t id0 = (size_t)blockIdx.x * blockDim.x + threadIdx.x;

    for (size_t i = id0; i < (size_t)TT * BB * DD; i += stride) {
        size_t m = i >> 9;
        int k = (int)(i & 511);
        int t = (int)(m >> 6);
        int r = (int)(m & 63);
        float v = x[(size_t)r * (TT * DD) + (size_t)t * DD + k];
        __nv_bfloat16 hi = __float2bfloat16(v);
        g_xhi[i] = hi;
        g_xlo[i] = __float2bfloat16(v - __bfloat162float(hi));
    }

    for (size_t i = id0; i < (size_t)NG * DD; i += stride) {
        int n = (int)(i & (NG - 1));
        int k = (int)(i >> 11);
        float v = W[(size_t)(HH + k) * NG + n];
        __nv_bfloat16 hi = __float2bfloat16(v);
        g_wthi[(size_t)n * DD + k] = hi;
        g_wtlo[(size_t)n * DD + k] = __float2bfloat16(v - __bfloat162float(hi));
    }
}

// ---------------------------------------------------------------------------
// Kernel 0b: tiny per-replay state reset (separate launch: shifts the fixed
// ncu capture slot onto xw_mma).
// ---------------------------------------------------------------------------
__global__ void __launch_bounds__(256) hinit_kernel() {
    int idx = blockIdx.x * blockDim.x + threadIdx.x;
    if (idx == 0) g_bar = 0ULL;
    for (int i = idx; i < BB * HH; i += gridDim.x * blockDim.x) {
        g_hbf_hi[0][i] = __float2bfloat16(0.0f);
        g_hbf_lo[0][i] = __float2bfloat16(0.0f);
    }
}

// ---------------------------------------------------------------------------
// Kernel 1: bf16 3-term split GEMM via mma.sync, cp.async double-buffered.
// CTA tile 128x128, 8 warps (warp tile 32x64), K chunked x32, 2 stages.
// ---------------------------------------------------------------------------
#define KP 40                     // padded smem k-stride (80 B rows)
#define XT (128 * KP)             // elems per tile
#define XW_STAGE_B (4 * XT * 2)   // bytes per stage (4 tiles)
#define XW_SMEM (2 * XW_STAGE_B)  // 81920 B

__global__ void __launch_bounds__(256, 2) xw_mma(const float* __restrict__ bias) {
    extern __shared__ __align__(16) __nv_bfloat16 sbuf[];

    const int tid  = threadIdx.x;
    const int wid  = tid >> 5;
    const int lane = tid & 31;

    const int n0 = blockIdx.x * 128;
    const int m0 = blockIdx.y * 128;
    const int wm = (wid & 3) * 32;
    const int wn = (wid >> 2) * 64;

    const __nv_bfloat16* xh = g_xhi + (size_t)m0 * DD;
    const __nv_bfloat16* xl = g_xlo + (size_t)m0 * DD;
    const __nv_bfloat16* wh = g_wthi + (size_t)n0 * DD;
    const __nv_bfloat16* wl = g_wtlo + (size_t)n0 * DD;

    const uint32_t sb_u = smem_u32(sbuf);

    float cf[2][8][4];
#pragma unroll
    for (int mt = 0; mt < 2; ++mt)
#pragma unroll
        for (int nt = 0; nt < 8; ++nt)
#pragma unroll
            for (int i = 0; i < 4; ++i) cf[mt][nt][i] = 0.0f;

    // staging ids: each thread covers (row, row+64) x 8-elem segment
    const int srow = tid >> 2;
    const int sq   = (tid & 3) * 8;

    // fragment ids
    const int a_row = lane & 15;
    const int a_col = (lane >> 4) << 3;
    const int b_row = lane & 7;
    const int b_col = ((lane >> 3) & 1) << 3;

#define XW_ISSUE(K0, ST) do {                                                  \
        uint32_t sbase = sb_u + (uint32_t)(ST) * XW_STAGE_B;                   \
        _Pragma("unroll")                                                      \
        for (int i = 0; i < 2; ++i) {                                          \
            int row = srow + (i << 6);                                         \
            size_t go = (size_t)row * DD + (K0) + sq;                          \
            uint32_t so = sbase + (uint32_t)(row * KP + sq) * 2;               \
            CP_ASYNC16(so,              xh + go);                              \
            CP_ASYNC16(so + XT * 2,     xl + go);                              \
            CP_ASYNC16(so + 2 * XT * 2, wh + go);                              \
            CP_ASYNC16(so + 3 * XT * 2, wl + go);                              \
        }                                                                      \
        CP_COMMIT();                                                           \
    } while (0)

    XW_ISSUE(0, 0);

    for (int ci = 0; ci < 16; ++ci) {
        const int cur = ci & 1;
        if (ci < 15) {
            XW_ISSUE((ci + 1) * 32, cur ^ 1);
            CP_WAIT(1);
        } else {
            CP_WAIT(0);
        }
        __syncthreads();

        const uint32_t ah_u = sb_u + (uint32_t)cur * XW_STAGE_B;
        const uint32_t al_u = ah_u + XT * 2;
        const uint32_t bh_u = ah_u + 2 * XT * 2;
        const uint32_t bl_u = ah_u + 3 * XT * 2;

#pragma unroll
        for (int kk = 0; kk < 32; kk += 16) {
            uint32_t ah[2][4], al[2][4];
#pragma unroll
            for (int mt = 0; mt < 2; ++mt) {
                uint32_t off =
                    (uint32_t)(((wm + mt * 16 + a_row) * KP + kk + a_col) * 2);
                ldsm_x4(ah[mt][0], ah[mt][1], ah[mt][2], ah[mt][3], ah_u + off);
                ldsm_x4(al[mt][0], al[mt][1], al[mt][2], al[mt][3], al_u + off);
            }
#pragma unroll
            for (int nt = 0; nt < 8; ++nt) {
                uint32_t off =
                    (uint32_t)(((wn + nt * 8 + b_row) * KP + kk + b_col) * 2);
                uint32_t bh2[2], bl2[2];
                ldsm_x2(bh2[0], bh2[1], bh_u + off);
                ldsm_x2(bl2[0], bl2[1], bl_u + off);
#pragma unroll
                for (int mt = 0; mt < 2; ++mt) {
                    mma16816(cf[mt][nt], ah[mt], bh2);
                    mma16816(cf[mt][nt], ah[mt], bl2);
                    mma16816(cf[mt][nt], al[mt], bh2);
                }
            }
        }
        __syncthreads();
    }
#undef XW_ISSUE

    const int er = lane >> 2;
    const int ec = (lane & 3) << 1;
#pragma unroll
    for (int nt = 0; nt < 8; ++nt) {
        int coln = n0 + wn + nt * 8 + ec;
        float2 bv = *(const float2*)(bias + coln);
#pragma unroll
        for (int mt = 0; mt < 2; ++mt) {
            int rowm = m0 + wm + mt * 16 + er;
            float* d0 = g_xw + (size_t)rowm * NG + coln;
            float* d1 = g_xw + (size_t)(rowm + 8) * NG + coln;
            *(float2*)d0 = make_float2(cf[mt][nt][0] + bv.x, cf[mt][nt][1] + bv.y);
            *(float2*)d1 = make_float2(cf[mt][nt][2] + bv.x, cf[mt][nt][3] + bv.y);
        }
    }
}

// ---------------------------------------------------------------------------
// Kernel 2: persistent recurrent LSTM, tensor-pipe (unchanged from R6 pass).
// ---------------------------------------------------------------------------
#define LSTM_SMEM (2 * 64 * HP * 2 + 2 * 16 * HP * 2 + 64 * 17 * 4)

__global__ void __launch_bounds__(256, 1) lstm_rec(const float* __restrict__ W,
                                                   float* __restrict__ out) {
    extern __shared__ __align__(16) char smraw[];
    __nv_bfloat16* shh = (__nv_bfloat16*)smraw;     // h hi [64][HP]
    __nv_bfloat16* shl = shh + 64 * HP;             // h lo
    __nv_bfloat16* swh = shl + 64 * HP;             // W_h hi [16][HP]
    __nv_bfloat16* swl = swh + 16 * HP;             // W_h lo
    float* sz = (float*)(swl + 16 * HP);            // z tile [64][17]

    const int tid  = threadIdx.x;
    const int wid  = tid >> 5;
    const int lane = tid & 31;
    const int J0   = blockIdx.x * JW;

    for (int idx = tid; idx < 16 * 512; idx += 256) {
        int n = idx >> 9;
        int k = idx & 511;
        float v = W[(size_t)k * NG + ((n >> 2) << 9) + J0 + (n & 3)];
        __nv_bfloat16 hi = __float2bfloat16(v);
        swh[n * HP + k] = hi;
        swl[n * HP + k] = __float2bfloat16(v - __bfloat162float(hi));
    }
    __syncthreads();

    const int m0w = (wid & 3) * 16;
    const int n0w = (wid >> 2) * 8;

    const int a_row = lane & 15;
    const int a_col = (lane >> 4) << 3;
    const int b_row = lane & 7;
    const int b_col = ((lane >> 3) & 1) << 3;

    const uint32_t shh_u = smem_u32(shh);
    const uint32_t shl_u = smem_u32(shl);
    const uint32_t swh_u = smem_u32(swh);
    const uint32_t swl_u = smem_u32(swl);

    const int er  = lane >> 2;
    const int ec2 = (lane & 3) << 1;
    const int gc  = n0w + ec2;
    const int gcolv = ((gc >> 2) << 9) + J0 + (gc & 3);

    const int jj = tid >> 6;
    const int r  = tid & 63;
    float cst = 0.0f;

    __syncthreads();

    for (int t = 0; t < TT; ++t) {
        const __nv_bfloat16* ghi = g_hbf_hi[t & 1];
        const __nv_bfloat16* glo = g_hbf_lo[t & 1];

#pragma unroll
        for (int cch = 0; cch < 4; ++cch) {
#pragma unroll
            for (int j = 0; j < 4; ++j) {
                int idx = tid + (j << 8);
                int row = idx >> 4;
                int seg = idx & 15;
                int eoff = row * HP + cch * 128 + seg * 8;
                int goff = row * 512 + cch * 128 + seg * 8;
                CP_ASYNC16(shh_u + eoff * 2, ghi + goff);
                CP_ASYNC16(shl_u + eoff * 2, glo + goff);
            }
            CP_COMMIT();
        }

        const float* xwp = g_xw + ((size_t)t * 64 + m0w + er) * NG + gcolv;
        float2 x0 = *(const float2*)xwp;
        float2 x1 = *(const float2*)(xwp + 8 * NG);
        float chh[4] = {x0.x, x0.y, x1.x, x1.y};
        float chl[4] = {0.f, 0.f, 0.f, 0.f};
        float clh[4] = {0.f, 0.f, 0.f, 0.f};

#define LSTM_CHUNK(CCH, WAITN)                                                 \
        {                                                                      \
            CP_WAIT(WAITN);                                                    \
            __syncthreads();                                                   \
            _Pragma("unroll")                                                  \
            for (int ks8 = 0; ks8 < 8; ++ks8) {                                \
                uint32_t aoff = (uint32_t)(((m0w + a_row) * HP +               \
                                 CCH * 128 + ks8 * 16 + a_col) * 2);           \
                uint32_t boff = (uint32_t)(((n0w + b_row) * HP +               \
                                 CCH * 128 + ks8 * 16 + b_col) * 2);           \
                uint32_t ah[4], al[4], bh2[2], bl2[2];                         \
                ldsm_x4(ah[0], ah[1], ah[2], ah[3], shh_u + aoff);             \
                ldsm_x4(al[0], al[1], al[2], al[3], shl_u + aoff);             \
                ldsm_x2(bh2[0], bh2[1], swh_u + boff);                         \
                ldsm_x2(bl2[0], bl2[1], swl_u + boff);                         \
                mma16816(chh, ah, bh2);                                        \
                mma16816(chl, ah, bl2);                                        \
                mma16816(clh, al, bh2);                                        \
            }                                                                  \
        }
        LSTM_CHUNK(0, 3)
        LSTM_CHUNK(1, 2)
        LSTM_CHUNK(2, 1)
        LSTM_CHUNK(3, 0)
#undef LSTM_CHUNK

        sz[(m0w + er) * 17 + gc]         = chh[0] + chl[0] + clh[0];
        sz[(m0w + er) * 17 + gc + 1]     = chh[1] + chl[1] + clh[1];
        sz[(m0w + er + 8) * 17 + gc]     = chh[2] + chl[2] + clh[2];
        sz[(m0w + er + 8) * 17 + gc + 1] = chh[3] + chl[3] + clh[3];
        __syncthreads();

        float zf = sz[r * 17 + jj];
        float zi = sz[r * 17 + 4 + jj];
        float zo = sz[r * 17 + 8 + jj];
        float zc = sz[r * 17 + 12 + jj];
        cst = sigf(zf) * cst + sigf(zi) * zc;
        float h = sigf(zo) * cst;

        out[(size_t)r * (TT * HH) + (size_t)t * HH + J0 + jj] = h;
        __nv_bfloat16 hhi = __float2bfloat16(h);
        __nv_bfloat16 hlo = __float2bfloat16(h - __bfloat162float(hhi));
        g_hbf_hi[(t + 1) & 1][r * 512 + J0 + jj] = hhi;
        g_hbf_lo[(t + 1) & 1][r * 512 + J0 + jj] = hlo;

        __threadfence();
        __syncthreads();
        if (tid == 0) {
            atomicAdd(&g_bar, 1ULL);
            unsigned long long target = (unsigned long long)(t + 1) * GCTA;
            while (*(volatile unsigned long long*)&g_bar < target) { }
        }
        __syncthreads();
    }
}

// ---------------------------------------------------------------------------
extern "C" void kernel_launch(void* const* d_in, const int* in_sizes, int n_in,
                              void* d_out, int out_size) {
    const float* x = (const float*)d_in[0];   // [64, 512, 512]
    const float* W = (const float*)d_in[1];   // [1024, 2048]
    const float* b = (const float*)d_in[2];   // [2048]
    float* out = (float*)d_out;               // [64, 512, 512]

    conv_kernel<<<1024, 256>>>(x, W);
    hinit_kernel<<<32, 256>>>();

    cudaFuncSetAttribute(xw_mma, cudaFuncAttributeMaxDynamicSharedMemorySize,
                         XW_SMEM);
    dim3 g1(NG / 128, (TT * BB) / 128);       // (16, 256)
    xw_mma<<<g1, 256, XW_SMEM>>>(b);

    cudaFuncSetAttribute(lstm_rec, cudaFuncAttributeMaxDynamicSharedMemorySize,
                         LSTM_SMEM);
    lstm_rec<<<GCTA, 256, LSTM_SMEM>>>(W, out);
}